// round 7
// baseline (speedup 1.0000x reference)
#include <cuda_runtime.h>
#include <cuda_bf16.h>

#define DIMV   2048
#define SV     4
#define NTV    5          // S + V
#define NV     2048
#define BV     4
#define TPB    128
#define NWARP  (TPB / 32)
#define CHUNKS (DIMV / (4 * TPB))   // 4 float4 chunks per thread per row
#define QUADS  (DIMV / 4)
#define EPSV   1e-5f

typedef unsigned long long u64;

// ---- packed f32x2 helpers (Blackwell FFMA2/FADD2/FMUL2 via PTX) ----
__device__ __forceinline__ u64 pk2(float lo, float hi) {
    u64 r; asm("mov.b64 %0, {%1, %2};" : "=l"(r) : "f"(lo), "f"(hi)); return r;
}
__device__ __forceinline__ float2 upk2(u64 v) {
    float2 f; asm("mov.b64 {%0, %1}, %2;" : "=f"(f.x), "=f"(f.y) : "l"(v)); return f;
}
__device__ __forceinline__ u64 fma2p(u64 a, u64 b, u64 c) {
    u64 r; asm("fma.rn.f32x2 %0, %1, %2, %3;" : "=l"(r) : "l"(a), "l"(b), "l"(c)); return r;
}
__device__ __forceinline__ u64 add2p(u64 a, u64 b) {
    u64 r; asm("add.rn.f32x2 %0, %1, %2;" : "=l"(r) : "l"(a), "l"(b)); return r;
}
__device__ __forceinline__ u64 mul2p(u64 a, u64 b) {
    u64 r; asm("mul.rn.f32x2 %0, %1, %2;" : "=l"(r) : "l"(a), "l"(b)); return r;
}
__device__ __forceinline__ u64 bf2f2(unsigned p) {
    float2 c = __bfloat1622float2(*reinterpret_cast<__nv_bfloat162*>(&p));
    return pk2(c.x, c.y);
}

// Scratch (no device allocation allowed).
// g_gp[j][q]: uint4; component i (i=dim within quad q) = bf16x2(g[2j][dim], g[2j+1][dim])
// -> one cvt+mov yields the packed (gate t0, gate t1) pair for that dim.
__device__ uint4 g_gp[3][QUADS];
__device__ float g_gsum[6];        // column sums of the ROUNDED gate values

__global__ void prep_kernel(const float* __restrict__ w,
                            const float* __restrict__ afn,
                            const float* __restrict__ bfn) {
    __shared__ float sred[16][6];
    const int tid = threadIdx.x;          // 512 threads, 1 block; one per dim-quad
    const int d0  = tid * 4;

    float gv[6][4];
#pragma unroll
    for (int i = 0; i < 4; i++) {
        float wv = w[d0 + i];
#pragma unroll
        for (int t = 0; t < NTV; t++)
            gv[t][i] = wv * afn[(d0 + i) * NTV + t];
        gv[5][i] = wv * bfn[d0 + i];
    }

    float part[6] = {0.f, 0.f, 0.f, 0.f, 0.f, 0.f};
#pragma unroll
    for (int j = 0; j < 3; j++) {
        const int t0 = 2 * j, t1 = 2 * j + 1;
        unsigned comp[4];
#pragma unroll
        for (int i = 0; i < 4; i++) {
            __nv_bfloat162 h = __floats2bfloat162_rn(gv[t0][i], gv[t1][i]);
            comp[i] = *reinterpret_cast<unsigned*>(&h);
            float2 f = __bfloat1622float2(h);
            part[t0] += f.x;
            part[t1] += f.y;
        }
        uint4 u; u.x = comp[0]; u.y = comp[1]; u.z = comp[2]; u.w = comp[3];
        g_gp[j][tid] = u;
    }

#pragma unroll
    for (int u = 0; u < 6; u++)
#pragma unroll
        for (int o = 16; o > 0; o >>= 1)
            part[u] += __shfl_xor_sync(0xffffffffu, part[u], o);
    if ((tid & 31) == 0)
#pragma unroll
        for (int u = 0; u < 6; u++) sred[tid >> 5][u] = part[u];
    __syncthreads();
    if (tid < 6) {
        float tot = 0.f;
#pragma unroll
        for (int wp = 0; wp < 16; wp++) tot += sred[wp][tid];
        g_gsum[tid] = tot;
    }
}

__global__ __launch_bounds__(TPB, 6) void hyper_kernel(
    const float* __restrict__ res,
    const float* __restrict__ static_beta,
    const float* __restrict__ static_alpha,
    const float* __restrict__ p_ascale,
    const float* __restrict__ p_bscale,
    float* __restrict__ out)
{
    __shared__ float sred[NWARP][SV * 8];

    const int tid  = threadIdx.x;
    const int warp = tid >> 5;
    const int lane = tid & 31;

    const int token = blockIdx.x;              // 0 .. B*N-1
    const int b = token >> 11;
    const int n = token & (NV - 1);
    const size_t rowstride = (size_t)NV * DIMV;
    const float* base  = res + (size_t)(b * SV) * rowstride + (size_t)n * DIMV;
    float*       obase = out + (size_t)(b * SV) * rowstride + (size_t)n * DIMV;

    // ---- Fused pass A (all packed f32x2) ----
    // sum2[s]: (sum of even-pos, sum of odd-pos); ssq2[s] likewise.
    // d2[s][j]: (dot with gate 2j, dot with gate 2j+1).
    u64 sum2[SV], ssq2[SV], d2[SV][3];
    const u64 zero = 0;
#pragma unroll
    for (int s = 0; s < SV; s++) {
        sum2[s] = zero; ssq2[s] = zero;
#pragma unroll
        for (int j = 0; j < 3; j++) d2[s][j] = zero;
    }

#pragma unroll
    for (int k = 0; k < CHUNKS; k++) {
        const int idx = tid + k * TPB;
        ulonglong2 v[SV];
#pragma unroll
        for (int s = 0; s < SV; s++)
            v[s] = __ldg(((const ulonglong2*)(base + (size_t)s * rowstride)) + idx);

        u64 gp[3][4];
#pragma unroll
        for (int j = 0; j < 3; j++) {
            uint4 p = g_gp[j][idx];
            gp[j][0] = bf2f2(p.x); gp[j][1] = bf2f2(p.y);
            gp[j][2] = bf2f2(p.z); gp[j][3] = bf2f2(p.w);
        }

#pragma unroll
        for (int s = 0; s < SV; s++) {
            sum2[s] = add2p(sum2[s], add2p(v[s].x, v[s].y));
            ssq2[s] = fma2p(v[s].x, v[s].x, ssq2[s]);
            ssq2[s] = fma2p(v[s].y, v[s].y, ssq2[s]);

            float2 flo = upk2(v[s].x), fhi = upk2(v[s].y);
            u64 b0 = pk2(flo.x, flo.x), b1 = pk2(flo.y, flo.y);
            u64 b2 = pk2(fhi.x, fhi.x), b3 = pk2(fhi.y, fhi.y);
#pragma unroll
            for (int j = 0; j < 3; j++) {
                d2[s][j] = fma2p(b0, gp[j][0], d2[s][j]);
                d2[s][j] = fma2p(b1, gp[j][1], d2[s][j]);
                d2[s][j] = fma2p(b2, gp[j][2], d2[s][j]);
                d2[s][j] = fma2p(b3, gp[j][3], d2[s][j]);
            }
        }
    }

    // Unpack to 32 scalars: acc[s*8+f], f: 0=sum 1=ssq 2..7=dots
    float acc[32];
#pragma unroll
    for (int s = 0; s < SV; s++) {
        float2 fs = upk2(sum2[s]);  acc[s * 8 + 0] = fs.x + fs.y;
        float2 fq = upk2(ssq2[s]);  acc[s * 8 + 1] = fq.x + fq.y;
#pragma unroll
        for (int j = 0; j < 3; j++) {
            float2 fd = upk2(d2[s][j]);
            acc[s * 8 + 2 + 2 * j]     = fd.x;
            acc[s * 8 + 2 + 2 * j + 1] = fd.y;
        }
    }

    // Prefetch pass-C chunk 0 (L1 hits) to overlap the reduction bubble.
    ulonglong2 pf[SV];
#pragma unroll
    for (int s = 0; s < SV; s++)
        pf[s] = __ldg(((const ulonglong2*)(base + (size_t)s * rowstride)) + tid);

    // ---- Butterfly reduction: 32 values across 32 lanes in 31 shuffles ----
    {
        int cnt = 32;
#pragma unroll
        for (int o = 1; o <= 16; o <<= 1) {
            const int h = cnt >> 1;
            const bool up = (lane & o) != 0;
#pragma unroll
            for (int i = 0; i < h; i++) {
                float send = up ? acc[i] : acc[i + h];
                float recv = __shfl_xor_sync(0xffffffffu, send, o);
                float keep = up ? acc[i + h] : acc[i];
                acc[i] = keep + recv;
            }
            cnt = h;
        }
    }
    const int vidx = ((lane & 1) << 4) | ((lane & 2) << 2) | (lane & 4)
                   | ((lane & 8) >> 2) | ((lane & 16) >> 4);
    sred[warp][vidx] = acc[0];
    __syncthreads();   // the ONLY barrier

    // ---- Redundant per-warp finalize ----
    float tot = sred[0][lane];
#pragma unroll
    for (int w = 1; w < NWARP; w++) tot += sred[w][lane];

    const int s_own = lane >> 3;
    const int f     = lane & 7;
    const float tsum = __shfl_sync(0xffffffffu, tot, (lane & 24) | 0);
    const float tssq = __shfl_sync(0xffffffffu, tot, (lane & 24) | 1);
    const float mu   = tsum * (1.f / DIMV);
    const float var  = tssq * (1.f / DIMV) - mu * mu;
    const float rsig = rsqrtf(var + EPSV);

    const int j = (f >= 2) ? (f - 2) : 0;      // clamped for safe loads
    const float gs   = g_gsum[j];
    const float dotc = (tot - mu * gs) * rsig;
    const float th   = tanhf(dotc);
    float ab;
    if (f < 7) ab = th * p_ascale[0] + static_alpha[s_own * NTV + j];
    else       ab = th * p_bscale[0] + static_beta[s_own];

    // Fold into 4x4 mix matrix, broadcast as packed (C,C) pairs.
    const int cs = lane >> 2, csp = lane & 3;
    const float beta_s  = __shfl_sync(0xffffffffu, ab, cs * 8 + 7);
    const float alp_sp0 = __shfl_sync(0xffffffffu, ab, csp * 8 + 2);
    const float alp_sps = __shfl_sync(0xffffffffu, ab, csp * 8 + 3 + cs);
    const float Cl = beta_s * alp_sp0 + alp_sps;   // valid on lanes 0..15

    u64 Cp[SV][SV];
#pragma unroll
    for (int s = 0; s < SV; s++)
#pragma unroll
        for (int sp = 0; sp < SV; sp++) {
            float c = __shfl_sync(0xffffffffu, Cl, s * 4 + sp);
            Cp[s][sp] = pk2(c, c);
        }

    // ---- Pass C: re-read residuals (L1 hits), packed 4x4 mix, streaming stores ----
#pragma unroll
    for (int k = 0; k < CHUNKS; k++) {
        const int idx = tid + k * TPB;
        ulonglong2 v[SV];
        if (k == 0) {
#pragma unroll
            for (int s = 0; s < SV; s++) v[s] = pf[s];
        } else {
#pragma unroll
            for (int s = 0; s < SV; s++)
                v[s] = __ldg(((const ulonglong2*)(base + (size_t)s * rowstride)) + idx);
        }
#pragma unroll
        for (int s = 0; s < SV; s++) {
            u64 olo = mul2p(Cp[s][0], v[0].x);
            u64 ohi = mul2p(Cp[s][0], v[0].y);
#pragma unroll
            for (int sp = 1; sp < SV; sp++) {
                olo = fma2p(Cp[s][sp], v[sp].x, olo);
                ohi = fma2p(Cp[s][sp], v[sp].y, ohi);
            }
            u64* optr = ((u64*)(obase + (size_t)s * rowstride)) + 2 * idx;
            asm volatile("st.global.cs.v2.u64 [%0], {%1, %2};"
                         :: "l"(optr), "l"(olo), "l"(ohi) : "memory");
        }
    }
}

extern "C" void kernel_launch(void* const* d_in, const int* in_sizes, int n_in,
                              void* d_out, int out_size) {
    const float* res    = (const float*)d_in[0];
    const float* w      = (const float*)d_in[1];
    const float* sbeta  = (const float*)d_in[2];
    const float* salpha = (const float*)d_in[3];
    const float* afn    = (const float*)d_in[4];
    const float* ascale = (const float*)d_in[5];
    const float* bfn    = (const float*)d_in[6];
    const float* bscale = (const float*)d_in[7];
    float* out = (float*)d_out;

    prep_kernel<<<1, 512>>>(w, afn, bfn);
    hyper_kernel<<<BV * NV, TPB>>>(res, sbeta, salpha, ascale, bscale, out);
}

// round 8
// speedup vs baseline: 1.2242x; 1.2242x over previous
#include <cuda_runtime.h>
#include <cuda_bf16.h>

#define DIMV   2048
#define SV     4
#define NTV    5          // S + V
#define NV     2048
#define BV     4
#define TPB    128
#define NWARP  (TPB / 32)
#define QUADS  (DIMV / 4)           // 512 float4 groups per row
#define ACHUNK 8                    // pass-A chunks per warp (256 quads / 32 lanes)
#define CCHUNK 4                    // pass-C chunks per warp (128 quads / 32 lanes)
#define EPSV   1e-5f

// Scratch (no device allocation allowed).
// g_gp[j][q]: uint4 holding gates t=2j,2j+1 for dim-quad q, bf16-packed:
//   .x = bf16x2(g[2j][0],   g[2j][1])   .y = bf16x2(g[2j][2],   g[2j][3])
//   .z = bf16x2(g[2j+1][0], g[2j+1][1]) .w = bf16x2(g[2j+1][2], g[2j+1][3])
__device__ uint4 g_gp[3][QUADS];
__device__ float g_gsum[6];        // column sums of the ROUNDED gate values

__global__ void prep_kernel(const float* __restrict__ w,
                            const float* __restrict__ afn,
                            const float* __restrict__ bfn) {
    __shared__ float sred[16][6];
    const int tid = threadIdx.x;          // 512 threads, 1 block; one per dim-quad
    const int d0  = tid * 4;

    float gv[6][4];
#pragma unroll
    for (int i = 0; i < 4; i++) {
        float wv = w[d0 + i];
#pragma unroll
        for (int t = 0; t < NTV; t++)
            gv[t][i] = wv * afn[(d0 + i) * NTV + t];
        gv[5][i] = wv * bfn[d0 + i];
    }

    float part[6];
#pragma unroll
    for (int j = 0; j < 3; j++) {
        const int t0 = 2 * j, t1 = 2 * j + 1;
        __nv_bfloat162 hx = __floats2bfloat162_rn(gv[t0][0], gv[t0][1]);
        __nv_bfloat162 hy = __floats2bfloat162_rn(gv[t0][2], gv[t0][3]);
        __nv_bfloat162 hz = __floats2bfloat162_rn(gv[t1][0], gv[t1][1]);
        __nv_bfloat162 hw = __floats2bfloat162_rn(gv[t1][2], gv[t1][3]);
        uint4 u;
        u.x = *reinterpret_cast<unsigned*>(&hx);
        u.y = *reinterpret_cast<unsigned*>(&hy);
        u.z = *reinterpret_cast<unsigned*>(&hz);
        u.w = *reinterpret_cast<unsigned*>(&hw);
        g_gp[j][tid] = u;
        float2 fx = __bfloat1622float2(hx), fy = __bfloat1622float2(hy);
        float2 fz = __bfloat1622float2(hz), fw = __bfloat1622float2(hw);
        part[t0] = fx.x + fx.y + fy.x + fy.y;
        part[t1] = fz.x + fz.y + fw.x + fw.y;
    }

#pragma unroll
    for (int u = 0; u < 6; u++)
#pragma unroll
        for (int o = 16; o > 0; o >>= 1)
            part[u] += __shfl_xor_sync(0xffffffffu, part[u], o);
    if ((tid & 31) == 0)
#pragma unroll
        for (int u = 0; u < 6; u++) sred[tid >> 5][u] = part[u];
    __syncthreads();
    if (tid < 6) {
        float tot = 0.f;
#pragma unroll
        for (int wp = 0; wp < 16; wp++) tot += sred[wp][tid];
        g_gsum[tid] = tot;
    }
}

__global__ __launch_bounds__(TPB, 8) void hyper_kernel(
    const float* __restrict__ res,
    const float* __restrict__ static_beta,
    const float* __restrict__ static_alpha,
    const float* __restrict__ p_ascale,
    const float* __restrict__ p_bscale,
    float* __restrict__ out)
{
    __shared__ float sred[NWARP][16];

    const int tid  = threadIdx.x;
    const int warp = tid >> 5;
    const int lane = tid & 31;

    const int token = blockIdx.x;              // 0 .. B*N-1
    const int b = token >> 11;
    const int n = token & (NV - 1);
    const size_t rowstride = (size_t)NV * DIMV;
    const float* base  = res + (size_t)(b * SV) * rowstride + (size_t)n * DIMV;
    float*       obase = out + (size_t)(b * SV) * rowstride + (size_t)n * DIMV;

    // ---- Pass A, stream-pair split:
    //   warps 0,1 -> streams {0,1}; warps 2,3 -> streams {2,3}
    //   warp&1 selects the dim half. Each warp: 2 streams x 1024 dims. ----
    const int spair = warp >> 1;               // 0 or 1
    const int half  = warp & 1;                // 0 or 1
    const float* pb0 = base + (size_t)(2 * spair)     * rowstride;
    const float* pb1 = base + (size_t)(2 * spair + 1) * rowstride;

    float acc[16];                              // [sidx*8+f] f:0=sum 1=ssq 2..7=dots
#pragma unroll
    for (int u = 0; u < 16; u++) acc[u] = 0.f;

#pragma unroll
    for (int k = 0; k < ACHUNK; k++) {
        const int idx = half * 256 + lane + k * 32;
        float4 v0 = __ldg(&((const float4*)pb0)[idx]);
        float4 v1 = __ldg(&((const float4*)pb1)[idx]);

        acc[0] += v0.x + v0.y + v0.z + v0.w;
        acc[1] += v0.x * v0.x + v0.y * v0.y + v0.z * v0.z + v0.w * v0.w;
        acc[8] += v1.x + v1.y + v1.z + v1.w;
        acc[9] += v1.x * v1.x + v1.y * v1.y + v1.z * v1.z + v1.w * v1.w;

#pragma unroll
        for (int j = 0; j < 3; j++) {
            uint4 p = g_gp[j][idx];
            float2 fx = __bfloat1622float2(*reinterpret_cast<__nv_bfloat162*>(&p.x));
            float2 fy = __bfloat1622float2(*reinterpret_cast<__nv_bfloat162*>(&p.y));
            float2 fz = __bfloat1622float2(*reinterpret_cast<__nv_bfloat162*>(&p.z));
            float2 fw = __bfloat1622float2(*reinterpret_cast<__nv_bfloat162*>(&p.w));
            acc[2 + 2 * j]      += v0.x * fx.x + v0.y * fx.y + v0.z * fy.x + v0.w * fy.y;
            acc[2 + 2 * j + 1]  += v0.x * fz.x + v0.y * fz.y + v0.z * fw.x + v0.w * fw.y;
            acc[10 + 2 * j]     += v1.x * fx.x + v1.y * fx.y + v1.z * fy.x + v1.w * fy.y;
            acc[10 + 2 * j + 1] += v1.x * fz.x + v1.y * fz.y + v1.z * fw.x + v1.w * fw.y;
        }
    }

    // ---- Butterfly: 16 values over 32 lanes, 4 stages + one xor-16 fold ----
    {
        int cnt = 16;
#pragma unroll
        for (int o = 1; o <= 8; o <<= 1) {
            const int h = cnt >> 1;
            const bool up = (lane & o) != 0;
#pragma unroll
            for (int i = 0; i < h; i++) {
                float send = up ? acc[i] : acc[i + h];
                float recv = __shfl_xor_sync(0xffffffffu, send, o);
                float keep = up ? acc[i + h] : acc[i];
                acc[i] = keep + recv;
            }
            cnt = h;
        }
        acc[0] += __shfl_xor_sync(0xffffffffu, acc[0], 16);
    }
    // lane l (l<16) owns value index bitrev4(l)
    const int vidx = ((lane & 1) << 3) | ((lane & 2) << 1)
                   | ((lane & 4) >> 1) | ((lane & 8) >> 3);
    if (lane < 16) sred[warp][vidx] = acc[0];
    __syncthreads();   // the ONLY barrier

    // ---- Redundant per-warp finalize: lane u owns (s_own = u>>3, f = u&7) ----
    const int s_own = lane >> 3;
    const int f     = lane & 7;
    const int wb    = (s_own >> 1) * 2;        // warp pair holding stream s_own
    const int off   = (s_own & 1) * 8 + f;
    float tot = sred[wb][off] + sred[wb + 1][off];

    const float tsum = __shfl_sync(0xffffffffu, tot, (lane & 24) | 0);
    const float tssq = __shfl_sync(0xffffffffu, tot, (lane & 24) | 1);
    const float mu   = tsum * (1.f / DIMV);
    const float var  = tssq * (1.f / DIMV) - mu * mu;
    const float rsig = rsqrtf(var + EPSV);

    const int j = (f >= 2) ? (f - 2) : 0;      // clamped for safe loads
    const float gs   = g_gsum[j];
    const float dotc = (tot - mu * gs) * rsig;
    const float th   = tanhf(dotc);
    float ab;
    if (f < 7) ab = th * p_ascale[0] + static_alpha[s_own * NTV + j];
    else       ab = th * p_bscale[0] + static_beta[s_own];
    // lanes f=2..6 hold alpha[s][0..4]; lane f=7 holds beta[s]; f<2 garbage.

    // Fold into 4x4 mix matrix on lanes 0..15, then broadcast.
    const int cs = lane >> 2, csp = lane & 3;
    const float beta_s  = __shfl_sync(0xffffffffu, ab, cs * 8 + 7);
    const float alp_sp0 = __shfl_sync(0xffffffffu, ab, csp * 8 + 2);
    const float alp_sps = __shfl_sync(0xffffffffu, ab, csp * 8 + 3 + cs);
    const float Cl = beta_s * alp_sp0 + alp_sps;   // valid on lanes 0..15

    float Cm[SV][SV];
#pragma unroll
    for (int s = 0; s < SV; s++)
#pragma unroll
        for (int sp = 0; sp < SV; sp++)
            Cm[s][sp] = __shfl_sync(0xffffffffu, Cl, s * 4 + sp);

    // ---- Pass C: warp w handles quads [w*128, (w+1)*128); re-read all 4
    //      streams (L1/L2 hits), 4x4 mix, streaming stores ----
#pragma unroll
    for (int k = 0; k < CCHUNK; k++) {
        const int idx = warp * 128 + lane + k * 32;
        float4 v[SV];
#pragma unroll
        for (int s = 0; s < SV; s++)
            v[s] = __ldg(&((const float4*)(base + (size_t)s * rowstride))[idx]);
#pragma unroll
        for (int s = 0; s < SV; s++) {
            float4 o;
            o.x = Cm[s][0] * v[0].x; o.y = Cm[s][0] * v[0].y;
            o.z = Cm[s][0] * v[0].z; o.w = Cm[s][0] * v[0].w;
#pragma unroll
            for (int sp = 1; sp < SV; sp++) {
                o.x += Cm[s][sp] * v[sp].x;
                o.y += Cm[s][sp] * v[sp].y;
                o.z += Cm[s][sp] * v[sp].z;
                o.w += Cm[s][sp] * v[sp].w;
            }
            __stcs(&((float4*)(obase + (size_t)s * rowstride))[idx], o);
        }
    }
}

extern "C" void kernel_launch(void* const* d_in, const int* in_sizes, int n_in,
                              void* d_out, int out_size) {
    const float* res    = (const float*)d_in[0];
    const float* w      = (const float*)d_in[1];
    const float* sbeta  = (const float*)d_in[2];
    const float* salpha = (const float*)d_in[3];
    const float* afn    = (const float*)d_in[4];
    const float* ascale = (const float*)d_in[5];
    const float* bfn    = (const float*)d_in[6];
    const float* bscale = (const float*)d_in[7];
    float* out = (float*)d_out;

    prep_kernel<<<1, 512>>>(w, afn, bfn);
    hyper_kernel<<<BV * NV, TPB>>>(res, sbeta, salpha, ascale, bscale, out);
}